// round 17
// baseline (speedup 1.0000x reference)
#include <cuda_runtime.h>
#include <math.h>

#define BATCH 4
#define CIN   64
#define COUT  64
#define H_    96
#define W_    320
#define HW    (H_ * W_)

#define DPX   128
#define APAD  132
#define NCHK  (HW / DPX)   // 240

typedef unsigned long long ull;

#define FMA2(d, a, b) asm("fma.rn.f32x2 %0, %1, %2, %0;" : "+l"(d) : "l"(a), "l"(b))
__device__ __forceinline__ ull pack2(float lo, float hi) {
    ull r;
    asm("mov.b64 %0, {%1, %2};" : "=l"(r) : "f"(lo), "f"(hi));
    return r;
}
__device__ __forceinline__ void unpack2(ull v, float& lo, float& hi) {
    asm("mov.b64 {%0, %1}, %2;" : "=f"(lo), "=f"(hi) : "l"(v));
}

// ---------------- scratch (static device globals; no allocations) ----------
__device__ float g_buf[BATCH * 32];
__device__ float l_buf[BATCH * 32 * HW];
__device__ float off_buf[BATCH * 18 * HW];
__device__ float mask_buf[BATCH * 9 * HW];
__device__ __align__(256) float convw_t[9 * 64 * 64];   // deform  [k][ci][co64]
__device__ __align__(256) float lmw_t[9 * 64 * 48];     // loc+mask [k][ci][co48]
__device__ __align__(256) float fusew_t[9 * 64 * 32];   // fuse    [k][ci][co32]
__device__ __align__(256) float w2t_loc[32 * 32];       // [c1][c2]
__device__ __align__(256) float w2t_fuse[32 * 32];      // [c1][c2 pad]
__device__ __align__(256) float lmb[48];                // loc_b1(32)+mask_b(9)+0

// ---------------- prep: all weight transposes -------------------------------
__global__ void prep_kernel(const float* __restrict__ conv_w,
                            const float* __restrict__ loc_w1,
                            const float* __restrict__ mask_w,
                            const float* __restrict__ fuse_w1,
                            const float* __restrict__ loc_w2,
                            const float* __restrict__ fuse_w2,
                            const float* __restrict__ loc_b1,
                            const float* __restrict__ mask_b)
{
    int idx0 = blockIdx.x * blockDim.x + threadIdx.x;
    int stride = gridDim.x * blockDim.x;
    for (int i = idx0; i < 9 * 64 * 64; i += stride) {
        int co = i & 63, ci = (i >> 6) & 63, k = i >> 12;
        convw_t[i] = conv_w[(co * 64 + ci) * 9 + k];
    }
    for (int i = idx0; i < 9 * 64 * 48; i += stride) {
        int co = i % 48, t = i / 48, ci = t & 63, k = t >> 6;
        float v = 0.f;
        if (co < 32) v = loc_w1[(co * 64 + ci) * 9 + k];
        else if (co < 41) v = mask_w[((co - 32) * 64 + ci) * 9 + k];
        lmw_t[(k * 64 + ci) * 48 + co] = v;
    }
    for (int i = idx0; i < 9 * 64 * 32; i += stride) {
        int co = i & 31, t = i >> 5, ci = t & 63, k = t >> 6;
        fusew_t[i] = fuse_w1[(co * 64 + ci) * 9 + k];
    }
    for (int i = idx0; i < 32 * 32; i += stride) {
        int c2 = i & 31, c1 = i >> 5;
        w2t_loc[i] = loc_w2[c2 * 32 + c1];
        w2t_fuse[i] = (c2 < 18) ? fuse_w2[c2 * 32 + c1] : 0.f;
    }
    if (idx0 < 48) {
        float v = 0.f;
        if (idx0 < 32) v = loc_b1[idx0];
        else if (idx0 < 41) v = mask_b[idx0 - 32];
        lmb[idx0] = v;
    }
}

// ---------------- Kernel A: tiny MLP for g (B x 32) ------------------------
__global__ void g_kernel(const float* __restrict__ scale,
                         const float* __restrict__ w1, const float* __restrict__ b1,
                         const float* __restrict__ w2, const float* __restrict__ b2)
{
    int tid = threadIdx.x;
    if (tid >= BATCH * 32) return;
    int b = tid >> 5;
    int i = tid & 31;
    const float* s = scale + b * 5;
    float bs0 = s[4] - s[2];
    float bs1 = s[3] - s[1];
    float acc = b2[i];
    for (int j = 0; j < 64; j++) {
        float h = fmaf(bs0, w1[j * 2 + 0], fmaf(bs1, w1[j * 2 + 1], b1[j]));
        h = fmaxf(h, 0.f);
        acc = fmaf(h, w2[i * 64 + j], acc);
    }
    g_buf[b * 32 + i] = acc;
}

// ---------------- Kernel B: loc+mask as tiled GEMM -------------------------
// tile 128 px x 48 co (32 loc conv1 + 9 mask + 7 pad), 256 threads.
// thread tile: 8 px x 3 co, FMA2 over px pairs.
__global__ void __launch_bounds__(256) locmask_kernel(const float* __restrict__ x,
    const float* __restrict__ b2v)
{
    __shared__ __align__(16) char pool[22016];
    float* Bs   = (float*)pool;                       // 64*48  = 12288 B
    float* As   = (float*)(pool + 12288);             // 16*132 = 8448 B
    int*   sIdx = (int*)(pool + 12288 + 8448);        // 512 B
    float* sVf  = (float*)(pool + 12288 + 8448 + 512);// 512 B
    float* Ls   = (float*)pool;                       // epilogue: 32*132*4

    int tid    = threadIdx.x;
    int b      = blockIdx.x / NCHK;
    int pxbase = (blockIdx.x % NCHK) * DPX;
    const float* xb = x + (size_t)(b * CIN * HW);

    int co0  = (tid & 15) * 3;
    int px0  = (tid >> 4) * 8;
    int gpx  = tid & 127;
    int cig0 = (tid >> 7) * 8;

    ull acc[12];   // [pair i 0..3][co j 0..2]
    #pragma unroll
    for (int i = 0; i < 4; i++)
        #pragma unroll
        for (int j = 0; j < 3; j++) {
            float bv = lmb[co0 + j];
            acc[i * 3 + j] = pack2(bv, bv);
        }

    for (int k = 0; k < 9; k++) {
        __syncthreads();
        {   // stage W_k [64ci][48co]
            const float4* src = (const float4*)(lmw_t + k * 64 * 48);
            float4* dst = (float4*)Bs;
            #pragma unroll
            for (int r = 0; r < 3; r++)
                dst[r * 256 + tid] = src[r * 256 + tid];
        }
        if (tid < DPX) {
            int p = pxbase + tid;
            int h = p / W_;
            int w = p - h * W_;
            int yy = h + k / 3 - 1;
            int xx = w + k % 3 - 1;
            bool ok = ((unsigned)yy < (unsigned)H_) && ((unsigned)xx < (unsigned)W_);
            sIdx[tid] = ok ? (yy * W_ + xx) : 0;
            sVf[tid]  = ok ? 1.f : 0.f;
        }
        __syncthreads();

        int   gi = sIdx[gpx];
        float gv = sVf[gpx];

        for (int cig = 0; cig < 4; cig++) {
            __syncthreads();
            #pragma unroll
            for (int j = 0; j < 8; j++) {
                int cl = cig0 + j;
                As[cl * APAD + gpx] = gv * __ldg(xb + (size_t)((cig * 16 + cl) * HW) + gi);
            }
            __syncthreads();

            const float* brow = Bs + cig * 16 * 48 + co0;
            #pragma unroll 4
            for (int ci = 0; ci < 16; ci++) {
                float b0 = brow[ci * 48 + 0];
                float b1 = brow[ci * 48 + 1];
                float b2 = brow[ci * 48 + 2];
                ull bp0 = pack2(b0, b0), bp1 = pack2(b1, b1), bp2 = pack2(b2, b2);
                ulonglong2 A0 = *(const ulonglong2*)(As + ci * APAD + px0);
                ulonglong2 A1 = *(const ulonglong2*)(As + ci * APAD + px0 + 4);
                ull av[4] = {A0.x, A0.y, A1.x, A1.y};
                #pragma unroll
                for (int i = 0; i < 4; i++) {
                    FMA2(acc[i * 3 + 0], av[i], bp0);
                    FMA2(acc[i * 3 + 1], av[i], bp1);
                    FMA2(acc[i * 3 + 2], av[i], bp2);
                }
            }
        }
    }

    // epilogue part 1: relu -> Ls, sigmoid -> mask_buf
    __syncthreads();
    #pragma unroll
    for (int j = 0; j < 3; j++) {
        int co = co0 + j;
        float v[8];
        #pragma unroll
        for (int i = 0; i < 4; i++) unpack2(acc[i * 3 + j], v[2 * i], v[2 * i + 1]);
        if (co < 32) {
            #pragma unroll
            for (int i = 0; i < 8; i++) v[i] = fmaxf(v[i], 0.f);
            *(float4*)(Ls + co * APAD + px0)     = make_float4(v[0], v[1], v[2], v[3]);
            *(float4*)(Ls + co * APAD + px0 + 4) = make_float4(v[4], v[5], v[6], v[7]);
        } else if (co < 41) {
            #pragma unroll
            for (int i = 0; i < 8; i++) v[i] = 1.f / (1.f + expf(-v[i]));
            float* mo = mask_buf + (size_t)(b * 9 + (co - 32)) * HW + pxbase + px0;
            *(float4*)mo       = make_float4(v[0], v[1], v[2], v[3]);
            *(float4*)(mo + 4) = make_float4(v[4], v[5], v[6], v[7]);
        }
    }
    __syncthreads();

    // epilogue part 2: 1x1 (32->32), thread = 1 c2 x 16 px
    {
        int c2  = tid & 31;
        int pxe = (tid >> 5) * 16;
        float bb = __ldg(b2v + c2);
        ull s[8];
        #pragma unroll
        for (int i = 0; i < 8; i++) s[i] = pack2(bb, bb);
        #pragma unroll 4
        for (int c1 = 0; c1 < 32; c1++) {
            float wv = __ldg(w2t_loc + c1 * 32 + c2);
            ull wp = pack2(wv, wv);
            const ulonglong2* ar = (const ulonglong2*)(Ls + c1 * APAD + pxe);
            ulonglong2 A0 = ar[0], A1 = ar[1], A2 = ar[2], A3 = ar[3];
            FMA2(s[0], A0.x, wp); FMA2(s[1], A0.y, wp);
            FMA2(s[2], A1.x, wp); FMA2(s[3], A1.y, wp);
            FMA2(s[4], A2.x, wp); FMA2(s[5], A2.y, wp);
            FMA2(s[6], A3.x, wp); FMA2(s[7], A3.y, wp);
        }
        float* lo = l_buf + (size_t)(b * 32 + c2) * HW + pxbase + pxe;
        #pragma unroll
        for (int i = 0; i < 4; i++) {
            float v0, v1, v2, v3;
            unpack2(s[2 * i], v0, v1);
            unpack2(s[2 * i + 1], v2, v3);
            *(float4*)(lo + 4 * i) = make_float4(v0, v1, v2, v3);
        }
    }
}

// ---------------- Kernel C: fuse as tiled GEMM -----------------------------
// tile 128 px x 32 co; g-half of K needs no loads. 256 threads, 8px x 2co.
__global__ void __launch_bounds__(256) fuse_kernel(const float* __restrict__ b1v,
    const float* __restrict__ b2v)
{
    __shared__ __align__(16) char pool[17920];
    float* Bs   = (float*)pool;                        // 64*32 = 8192 B
    float* As   = (float*)(pool + 8192);               // 8448 B
    int*   sIdx = (int*)(pool + 8192 + 8448);          // 512 B
    float* sVf  = (float*)(pool + 8192 + 8448 + 512);  // 512 B
    float* gss  = (float*)(pool + 17664);              // 128 B (surviving)
    float* Ls   = (float*)pool;                        // epilogue

    int tid    = threadIdx.x;
    int b      = blockIdx.x / NCHK;
    int pxbase = (blockIdx.x % NCHK) * DPX;

    if (tid < 32) gss[tid] = g_buf[b * 32 + tid];

    int co0  = (tid & 15) * 2;
    int px0  = (tid >> 4) * 8;
    int gpx  = tid & 127;
    int cig0 = (tid >> 7) * 8;

    ull acc[8];   // [pair i 0..3][co j 0..1]
    #pragma unroll
    for (int i = 0; i < 4; i++)
        #pragma unroll
        for (int j = 0; j < 2; j++) {
            float bv = __ldg(b1v + co0 + j);
            acc[i * 2 + j] = pack2(bv, bv);
        }

    for (int k = 0; k < 9; k++) {
        __syncthreads();
        {
            const float4* src = (const float4*)(fusew_t + k * 64 * 32);
            float4* dst = (float4*)Bs;
            #pragma unroll
            for (int r = 0; r < 2; r++)
                dst[r * 256 + tid] = src[r * 256 + tid];
        }
        if (tid < DPX) {
            int p = pxbase + tid;
            int h = p / W_;
            int w = p - h * W_;
            int yy = h + k / 3 - 1;
            int xx = w + k % 3 - 1;
            bool ok = ((unsigned)yy < (unsigned)H_) && ((unsigned)xx < (unsigned)W_);
            sIdx[tid] = ok ? (yy * W_ + xx) : 0;
            sVf[tid]  = ok ? 1.f : 0.f;
        }
        __syncthreads();

        int   gi = sIdx[gpx];
        float gv = sVf[gpx];

        for (int cig = 0; cig < 4; cig++) {
            __syncthreads();
            if (cig < 2) {
                #pragma unroll
                for (int j = 0; j < 8; j++) {
                    int cl = cig0 + j;
                    As[cl * APAD + gpx] = gv * gss[cig * 16 + cl];
                }
            } else {
                const float* lb = l_buf + (size_t)(b * 32 + (cig - 2) * 16) * HW;
                #pragma unroll
                for (int j = 0; j < 8; j++) {
                    int cl = cig0 + j;
                    As[cl * APAD + gpx] = gv * __ldg(lb + (size_t)(cl * HW) + gi);
                }
            }
            __syncthreads();

            const float* brow = Bs + cig * 16 * 32 + co0;
            #pragma unroll 4
            for (int ci = 0; ci < 16; ci++) {
                float b0 = brow[ci * 32 + 0];
                float b1 = brow[ci * 32 + 1];
                ull bp0 = pack2(b0, b0), bp1 = pack2(b1, b1);
                ulonglong2 A0 = *(const ulonglong2*)(As + ci * APAD + px0);
                ulonglong2 A1 = *(const ulonglong2*)(As + ci * APAD + px0 + 4);
                ull av[4] = {A0.x, A0.y, A1.x, A1.y};
                #pragma unroll
                for (int i = 0; i < 4; i++) {
                    FMA2(acc[i * 2 + 0], av[i], bp0);
                    FMA2(acc[i * 2 + 1], av[i], bp1);
                }
            }
        }
    }

    // epilogue: relu -> Ls
    __syncthreads();
    #pragma unroll
    for (int j = 0; j < 2; j++) {
        int co = co0 + j;
        float v[8];
        #pragma unroll
        for (int i = 0; i < 4; i++) unpack2(acc[i * 2 + j], v[2 * i], v[2 * i + 1]);
        #pragma unroll
        for (int i = 0; i < 8; i++) v[i] = fmaxf(v[i], 0.f);
        *(float4*)(Ls + co * APAD + px0)     = make_float4(v[0], v[1], v[2], v[3]);
        *(float4*)(Ls + co * APAD + px0 + 4) = make_float4(v[4], v[5], v[6], v[7]);
    }
    __syncthreads();

    // 1x1 (32->18)
    {
        int c2  = tid & 31;
        int pxe = (tid >> 5) * 16;
        if (c2 < 18) {
            float bb = __ldg(b2v + c2);
            ull s[8];
            #pragma unroll
            for (int i = 0; i < 8; i++) s[i] = pack2(bb, bb);
            #pragma unroll 4
            for (int c1 = 0; c1 < 32; c1++) {
                float wv = __ldg(w2t_fuse + c1 * 32 + c2);
                ull wp = pack2(wv, wv);
                const ulonglong2* ar = (const ulonglong2*)(Ls + c1 * APAD + pxe);
                ulonglong2 A0 = ar[0], A1 = ar[1], A2 = ar[2], A3 = ar[3];
                FMA2(s[0], A0.x, wp); FMA2(s[1], A0.y, wp);
                FMA2(s[2], A1.x, wp); FMA2(s[3], A1.y, wp);
                FMA2(s[4], A2.x, wp); FMA2(s[5], A2.y, wp);
                FMA2(s[6], A3.x, wp); FMA2(s[7], A3.y, wp);
            }
            float* oo = off_buf + (size_t)(b * 18 + c2) * HW + pxbase + pxe;
            #pragma unroll
            for (int i = 0; i < 4; i++) {
                float v0, v1, v2, v3;
                unpack2(s[2 * i], v0, v1);
                unpack2(s[2 * i + 1], v2, v3);
                *(float4*)(oo + 4 * i) = make_float4(v0, v1, v2, v3);
            }
        }
    }
}

// ---------------- Kernel E: deformable conv as tiled GEMM (FMA2 math) ------
__global__ void __launch_bounds__(256) deform_kernel(const float* __restrict__ x,
    const float* __restrict__ bias, float* __restrict__ out)
{
    __shared__ float Bs[64 * 64];        // 16 KB
    __shared__ float As[16 * APAD];      // 8.25 KB
    __shared__ int   s_idx[4][DPX];
    __shared__ float s_wt[4][DPX];

    int tid    = threadIdx.x;
    int b      = blockIdx.x / NCHK;
    int pxbase = (blockIdx.x % NCHK) * DPX;

    const float* xb   = x + (size_t)(b * CIN * HW);
    const float* offb = off_buf + (size_t)(b * 18 * HW) + pxbase;
    const float* mb   = mask_buf + (size_t)(b * 9 * HW) + pxbase;

    int co0  = (tid & 15) * 4;
    int px0  = (tid >> 4) * 8;
    int gpx  = tid & 127;
    int cig0 = (tid >> 7) * 8;

    ull acc[16];   // [pair i 0..3][co j 0..3]
    #pragma unroll
    for (int i = 0; i < 4; i++)
        #pragma unroll
        for (int j = 0; j < 4; j++) {
            float bv = __ldg(bias + co0 + j);
            acc[i * 4 + j] = pack2(bv, bv);
        }

    for (int k = 0; k < 9; k++) {
        __syncthreads();
        {
            const float4* src = (const float4*)(convw_t + k * 4096);
            float4* dst = (float4*)Bs;
            #pragma unroll
            for (int r = 0; r < 4; r++)
                dst[r * 256 + tid] = src[r * 256 + tid];
        }
        if (tid < DPX) {
            int p = pxbase + tid;
            int h = p / W_;
            int w = p - h * W_;
            float dy = __ldg(offb + (k * 2 + 0) * HW + tid);
            float dx = __ldg(offb + (k * 2 + 1) * HW + tid);
            float mm = __ldg(mb + k * HW + tid);

            float ys = (float)(h + k / 3 - 1) + dy;
            float xs = (float)(w + k % 3 - 1) + dx;
            float fy = floorf(ys), fx = floorf(xs);
            int y0 = (int)fy, x0 = (int)fx;
            float wy = ys - fy, wx = xs - fx;

            bool vy0 = (unsigned)y0 < (unsigned)H_;
            bool vy1 = (unsigned)(y0 + 1) < (unsigned)H_;
            bool vx0 = (unsigned)x0 < (unsigned)W_;
            bool vx1 = (unsigned)(x0 + 1) < (unsigned)W_;

            int y0c = min(max(y0, 0), H_ - 1);
            int y1c = min(max(y0 + 1, 0), H_ - 1);
            int x0c = min(max(x0, 0), W_ - 1);
            int x1c = min(max(x0 + 1, 0), W_ - 1);

            s_idx[0][tid] = y0c * W_ + x0c;
            s_idx[1][tid] = y0c * W_ + x1c;
            s_idx[2][tid] = y1c * W_ + x0c;
            s_idx[3][tid] = y1c * W_ + x1c;
            s_wt[0][tid] = (vy0 && vx0) ? (1.f - wy) * (1.f - wx) * mm : 0.f;
            s_wt[1][tid] = (vy0 && vx1) ? (1.f - wy) * wx * mm : 0.f;
            s_wt[2][tid] = (vy1 && vx0) ? wy * (1.f - wx) * mm : 0.f;
            s_wt[3][tid] = (vy1 && vx1) ? wy * wx * mm : 0.f;
        }
        __syncthreads();

        int   i0 = s_idx[0][gpx], i1 = s_idx[1][gpx];
        int   i2 = s_idx[2][gpx], i3 = s_idx[3][gpx];
        float t0 = s_wt[0][gpx],  t1 = s_wt[1][gpx];
        float t2 = s_wt[2][gpx],  t3 = s_wt[3][gpx];

        for (int cig = 0; cig < 4; cig++) {
            __syncthreads();
            #pragma unroll
            for (int j = 0; j < 8; j++) {
                int cl = cig0 + j;
                const float* xc = xb + (size_t)((cig * 16 + cl) * HW);
                float v = t0 * __ldg(xc + i0);
                v = fmaf(t1, __ldg(xc + i1), v);
                v = fmaf(t2, __ldg(xc + i2), v);
                v = fmaf(t3, __ldg(xc + i3), v);
                As[cl * APAD + gpx] = v;
            }
            __syncthreads();

            const float* brow = Bs + cig * 16 * 64 + co0;
            #pragma unroll 4
            for (int ci = 0; ci < 16; ci++) {
                float4 b4 = *(const float4*)(brow + ci * 64);
                ull bp0 = pack2(b4.x, b4.x), bp1 = pack2(b4.y, b4.y);
                ull bp2 = pack2(b4.z, b4.z), bp3 = pack2(b4.w, b4.w);
                ulonglong2 A0 = *(const ulonglong2*)(As + ci * APAD + px0);
                ulonglong2 A1 = *(const ulonglong2*)(As + ci * APAD + px0 + 4);
                ull av[4] = {A0.x, A0.y, A1.x, A1.y};
                #pragma unroll
                for (int i = 0; i < 4; i++) {
                    FMA2(acc[i * 4 + 0], av[i], bp0);
                    FMA2(acc[i * 4 + 1], av[i], bp1);
                    FMA2(acc[i * 4 + 2], av[i], bp2);
                    FMA2(acc[i * 4 + 3], av[i], bp3);
                }
            }
        }
    }

    float* ob = out + (size_t)(b * COUT * HW) + pxbase + px0;
    #pragma unroll
    for (int j = 0; j < 4; j++) {
        float v[8];
        #pragma unroll
        for (int i = 0; i < 4; i++) unpack2(acc[i * 4 + j], v[2 * i], v[2 * i + 1]);
        *(float4*)(ob + (size_t)(co0 + j) * HW)     = make_float4(v[0], v[1], v[2], v[3]);
        *(float4*)(ob + (size_t)(co0 + j) * HW + 4) = make_float4(v[4], v[5], v[6], v[7]);
    }
}

// ---------------- launch ----------------------------------------------------
extern "C" void kernel_launch(void* const* d_in, const int* in_sizes, int n_in,
                              void* d_out, int out_size)
{
    const float* x        = (const float*)d_in[0];
    const float* scale    = (const float*)d_in[1];
    const float* glob_w1  = (const float*)d_in[2];
    const float* glob_b1  = (const float*)d_in[3];
    const float* glob_w2  = (const float*)d_in[4];
    const float* glob_b2  = (const float*)d_in[5];
    const float* loc_w1   = (const float*)d_in[6];
    const float* loc_b1   = (const float*)d_in[7];
    const float* loc_w2   = (const float*)d_in[8];
    const float* loc_b2   = (const float*)d_in[9];
    const float* fuse_w1  = (const float*)d_in[10];
    const float* fuse_b1  = (const float*)d_in[11];
    const float* fuse_w2  = (const float*)d_in[12];
    const float* fuse_b2  = (const float*)d_in[13];
    const float* mask_w   = (const float*)d_in[14];
    const float* mask_b   = (const float*)d_in[15];
    const float* conv_w   = (const float*)d_in[16];
    const float* conv_b   = (const float*)d_in[17];
    float* out = (float*)d_out;

    prep_kernel<<<160, 256>>>(conv_w, loc_w1, mask_w, fuse_w1,
                              loc_w2, fuse_w2, loc_b1, mask_b);
    g_kernel<<<1, 128>>>(scale, glob_w1, glob_b1, glob_w2, glob_b2);
    locmask_kernel<<<BATCH * NCHK, 256>>>(x, loc_b2);
    fuse_kernel<<<BATCH * NCHK, 256>>>(fuse_b1, fuse_b2);
    deform_kernel<<<BATCH * NCHK, 256>>>(x, conv_b, out);
}